// round 2
// baseline (speedup 1.0000x reference)
#include <cuda_runtime.h>
#include <cstdint>

#define OUTF 11008
#define INF  4096
#define BATCH 8
#define SPLITK 8
#define KCHUNK (INF / SPLITK)          // 512 columns per K-chunk
#define PAIRS_PER_CHUNK (KCHUNK / 2)   // 256 column-pairs (bytes) per row per chunk
#define BLOCKS_PER_CHUNK (KCHUNK / 32) // 16 q4 blocks per chunk
#define ROWS_PER_CTA 128
#define CTA_THREADS 128

// Packed f32x2 ops (Blackwell sm_103a).
__device__ __forceinline__ float2 ffma2(float2 a, float2 b, float2 c) {
    float2 d;
    asm("{\n\t"
        ".reg .b64 A,B,C,D;\n\t"
        "mov.b64 A,{%2,%3};\n\t"
        "mov.b64 B,{%4,%5};\n\t"
        "mov.b64 C,{%6,%7};\n\t"
        "fma.rn.f32x2 D,A,B,C;\n\t"
        "mov.b64 {%0,%1},D;\n\t"
        "}"
        : "=f"(d.x), "=f"(d.y)
        : "f"(a.x), "f"(a.y), "f"(b.x), "f"(b.y), "f"(c.x), "f"(c.y));
    return d;
}

__device__ __forceinline__ float2 fadd2(float2 a, float2 b) {
    float2 d;
    asm("{\n\t"
        ".reg .b64 A,B,D;\n\t"
        "mov.b64 A,{%2,%3};\n\t"
        "mov.b64 B,{%4,%5};\n\t"
        "add.rn.f32x2 D,A,B;\n\t"
        "mov.b64 {%0,%1},D;\n\t"
        "}"
        : "=f"(d.x), "=f"(d.y)
        : "f"(a.x), "f"(a.y), "f"(b.x), "f"(b.y));
    return d;
}

__device__ __forceinline__ float2 fmul2(float2 a, float2 b) {
    float2 d;
    asm("{\n\t"
        ".reg .b64 A,B,D;\n\t"
        "mov.b64 A,{%2,%3};\n\t"
        "mov.b64 B,{%4,%5};\n\t"
        "mul.rn.f32x2 D,A,B;\n\t"
        "mov.b64 {%0,%1},D;\n\t"
        "}"
        : "=f"(d.x), "=f"(d.y)
        : "f"(a.x), "f"(a.y), "f"(b.x), "f"(b.y));
    return d;
}

__global__ void zero_kernel(float* __restrict__ out, int n) {
    int i = blockIdx.x * blockDim.x + threadIdx.x;
    if (i < n) out[i] = 0.0f;
}

__global__ __launch_bounds__(CTA_THREADS)
void qlin_kernel(const float* __restrict__ x,
                 const int*   __restrict__ packed,
                 const float* __restrict__ scales,
                 float*       __restrict__ out) {
    // x chunk, transposed into column-pair-major float2s:
    // xs[jp*8 + r] = (x[r][kbase+2*jp], x[r][kbase+2*jp+1])
    __shared__ __align__(16) float2 xs[PAIRS_PER_CHUNK * BATCH];  // 16 KB

    const int tid   = threadIdx.x;
    const int kbase = blockIdx.y * KCHUNK;

    // Cooperative load of the x chunk (coalesced float2 reads from global).
    #pragma unroll
    for (int i = tid; i < PAIRS_PER_CHUNK * BATCH; i += CTA_THREADS) {
        int jp = i >> 3;        // column pair index
        int r  = i & 7;         // batch row
        const float2* xg = reinterpret_cast<const float2*>(x + (size_t)r * INF + kbase) + jp;
        xs[jp * BATCH + r] = *xg;
    }
    __syncthreads();

    const int warp = tid >> 5;
    const int lane = tid & 31;
    const int row  = blockIdx.x * ROWS_PER_CTA + warp * 32 + lane;  // output row (one per lane)

    // This row's packed "bytes" (one per int32) for this K-chunk:
    // 256 int32s = 64 int4s = 16 blocks * 4 int4.
    const int4*  pk = reinterpret_cast<const int4*>(packed + (size_t)row * (INF / 2) + (kbase >> 1));
    const float* sc = scales + (size_t)row * (INF / 32) + (kbase >> 5);

    float2 acc[BATCH];
    #pragma unroll
    for (int r = 0; r < BATCH; r++) acc[r] = make_float2(0.0f, 0.0f);

    // Double-buffered block loop: prefetch block blk+1 while processing blk.
    float s_cur = sc[0];
    int4 p_cur[4];
    #pragma unroll
    for (int i = 0; i < 4; i++) p_cur[i] = pk[i];

    for (int blk = 0; blk < BLOCKS_PER_CHUNK; blk++) {
        float s_nxt = 0.0f;
        int4 p_nxt[4];
        if (blk + 1 < BLOCKS_PER_CHUNK) {
            s_nxt = sc[blk + 1];
            #pragma unroll
            for (int i = 0; i < 4; i++) p_nxt[i] = pk[(blk + 1) * 4 + i];
        }

        const float2 s2   = make_float2(s_cur, s_cur);
        // exact: (2^23+n) - (2^23+8) = n-8 (Sterbenz), then single rounding in mul
        const float2 m8   = make_float2(-8388616.0f, -8388616.0f);  // -(2^23 + 8)

        int bytes[16];
        #pragma unroll
        for (int i = 0; i < 4; i++) {
            bytes[i * 4 + 0] = p_cur[i].x;
            bytes[i * 4 + 1] = p_cur[i].y;
            bytes[i * 4 + 2] = p_cur[i].z;
            bytes[i * 4 + 3] = p_cur[i].w;
        }

        #pragma unroll
        for (int b = 0; b < 16; b++) {
            const int v = bytes[b];
            // Magic-mantissa: float(0x4B000000 | n) = 2^23 + n exactly.
            const int lobits = (v & 15) | 0x4B000000;
            const int hibits = ((v >> 4) & 15) | 0x4B000000;
            float2 bits2 = make_float2(__int_as_float(lobits), __int_as_float(hibits));
            float2 q2 = fadd2(bits2, m8);        // exactly (n_lo-8, n_hi-8)
            float2 w2 = fmul2(q2, s2);           // (n-8)*s, one rounding

            const int jp = blk * 16 + b;
            const float4* xp = reinterpret_cast<const float4*>(&xs[jp * BATCH]);
            float4 x01 = xp[0];   // rows 0,1 pairs
            float4 x23 = xp[1];
            float4 x45 = xp[2];
            float4 x67 = xp[3];

            acc[0] = ffma2(w2, make_float2(x01.x, x01.y), acc[0]);
            acc[1] = ffma2(w2, make_float2(x01.z, x01.w), acc[1]);
            acc[2] = ffma2(w2, make_float2(x23.x, x23.y), acc[2]);
            acc[3] = ffma2(w2, make_float2(x23.z, x23.w), acc[3]);
            acc[4] = ffma2(w2, make_float2(x45.x, x45.y), acc[4]);
            acc[5] = ffma2(w2, make_float2(x45.z, x45.w), acc[5]);
            acc[6] = ffma2(w2, make_float2(x67.x, x67.y), acc[6]);
            acc[7] = ffma2(w2, make_float2(x67.z, x67.w), acc[7]);
        }

        s_cur = s_nxt;
        #pragma unroll
        for (int i = 0; i < 4; i++) p_cur[i] = p_nxt[i];
    }

    // Combine split-K partials.
    #pragma unroll
    for (int r = 0; r < BATCH; r++) {
        float v = acc[r].x + acc[r].y;
        atomicAdd(&out[(size_t)r * OUTF + row], v);
    }
}

extern "C" void kernel_launch(void* const* d_in, const int* in_sizes, int n_in,
                              void* d_out, int out_size) {
    const float* x      = (const float*)d_in[0];
    const int*   packed = (const int*)d_in[1];
    const float* scales = (const float*)d_in[2];
    float*       out    = (float*)d_out;

    zero_kernel<<<(out_size + 255) / 256, 256>>>(out, out_size);

    dim3 grid(OUTF / ROWS_PER_CTA, SPLITK);   // (86, 8)
    qlin_kernel<<<grid, CTA_THREADS>>>(x, packed, scales, out);
}

// round 3
// speedup vs baseline: 1.1289x; 1.1289x over previous
#include <cuda_runtime.h>
#include <cstdint>

#define OUTF 11008
#define INF  4096
#define BATCH 8
#define SPLITK 2
#define KCHUNK 1024                    // columns per smem chunk
#define CHUNKS_PER_CTA 2               // (INF / SPLITK) / KCHUNK
#define ROWS_PER_WARP 4
#define WARPS 8
#define CTA_THREADS 256
#define ROWS_PER_CTA (ROWS_PER_WARP * WARPS)   // 32

// Packed f32x2 ops (Blackwell sm_103a).
__device__ __forceinline__ float2 ffma2(float2 a, float2 b, float2 c) {
    float2 d;
    asm("{\n\t.reg .b64 A,B,C,D;\n\t"
        "mov.b64 A,{%2,%3};\n\tmov.b64 B,{%4,%5};\n\tmov.b64 C,{%6,%7};\n\t"
        "fma.rn.f32x2 D,A,B,C;\n\tmov.b64 {%0,%1},D;\n\t}"
        : "=f"(d.x), "=f"(d.y)
        : "f"(a.x), "f"(a.y), "f"(b.x), "f"(b.y), "f"(c.x), "f"(c.y));
    return d;
}
__device__ __forceinline__ float2 fadd2(float2 a, float2 b) {
    float2 d;
    asm("{\n\t.reg .b64 A,B,D;\n\t"
        "mov.b64 A,{%2,%3};\n\tmov.b64 B,{%4,%5};\n\t"
        "add.rn.f32x2 D,A,B;\n\tmov.b64 {%0,%1},D;\n\t}"
        : "=f"(d.x), "=f"(d.y) : "f"(a.x), "f"(a.y), "f"(b.x), "f"(b.y));
    return d;
}
__device__ __forceinline__ float2 fmul2(float2 a, float2 b) {
    float2 d;
    asm("{\n\t.reg .b64 A,B,D;\n\t"
        "mov.b64 A,{%2,%3};\n\tmov.b64 B,{%4,%5};\n\t"
        "mul.rn.f32x2 D,A,B;\n\tmov.b64 {%0,%1},D;\n\t}"
        : "=f"(d.x), "=f"(d.y) : "f"(a.x), "f"(a.y), "f"(b.x), "f"(b.y));
    return d;
}

__global__ void zero_kernel(float* __restrict__ out, int n) {
    int i = blockIdx.x * blockDim.x + threadIdx.x;
    if (i < n) out[i] = 0.0f;
}

__global__ __launch_bounds__(CTA_THREADS, 2)
void qlin_kernel(const float* __restrict__ x,
                 const int*   __restrict__ packed,
                 const float* __restrict__ scales,
                 float*       __restrict__ out) {
    // x chunk in smem, layout [col][batch] (8 floats = 32B per column),
    // XOR-swizzled on 16B chunks by bits [12:10] (== block index % 8) so that
    // lane-divergent LDS.128 (lanes own distinct 32-col blocks) are conflict-free.
    __shared__ __align__(16) float xs[KCHUNK * BATCH];  // 32 KB

    const int tid  = threadIdx.x;
    const int lane = tid & 31;
    const int warp = tid >> 5;
    const int rowbase = blockIdx.x * ROWS_PER_CTA + warp * ROWS_PER_WARP;
    const int xor_l = (lane & 7) << 4;          // swizzle term for this lane's block
    const char* xlane = (const char*)xs + (lane << 10);   // lane's 1KB column-block

    float2 acc[ROWS_PER_WARP][4];   // [row][batch-pair]
    #pragma unroll
    for (int i = 0; i < ROWS_PER_WARP; i++)
        #pragma unroll
        for (int p = 0; p < 4; p++) acc[i][p] = make_float2(0.f, 0.f);

    const float2 m8 = make_float2(-8388616.0f, -8388616.0f);  // -(2^23+8)

    for (int ch = 0; ch < CHUNKS_PER_CTA; ch++) {
        const int kbase = blockIdx.y * (INF / SPLITK) + ch * KCHUNK;

        __syncthreads();
        // Cooperative x load: thread t handles batch row (t&7), col-group (t>>3)*4.
        {
            const int r  = tid & 7;
            const int cg = (tid >> 3) << 2;   // 0,4,...,124
            #pragma unroll
            for (int pass = 0; pass < KCHUNK / 128; pass++) {
                const int c = pass * 128 + cg;
                float4 v = *reinterpret_cast<const float4*>(x + (size_t)r * INF + kbase + c);
                #pragma unroll
                for (int k = 0; k < 4; k++) {
                    int off = ((c + k) << 5) + (r << 2);
                    off ^= ((off >> 10) & 7) << 4;
                    *(float*)((char*)xs + off) = (&v.x)[k];
                }
            }
        }
        __syncthreads();

        const int blk = (kbase >> 5) + lane;    // global q4 block owned by this lane

        float s[ROWS_PER_WARP];
        const int4* pw[ROWS_PER_WARP];
        #pragma unroll
        for (int i = 0; i < ROWS_PER_WARP; i++) {
            const int row = rowbase + i;
            s[i]  = scales[(size_t)row * (INF / 32) + blk];
            pw[i] = reinterpret_cast<const int4*>(packed + (size_t)row * (INF / 2)) + (blk << 2);
        }

        #pragma unroll
        for (int jq = 0; jq < 4; jq++) {
            int4 w[ROWS_PER_WARP];
            #pragma unroll
            for (int i = 0; i < ROWS_PER_WARP; i++) w[i] = pw[i][jq];

            #pragma unroll
            for (int jb = 0; jb < 4; jb++) {
                const int j  = jq * 4 + jb;      // byte index within block -> cols 2j, 2j+1
                const int c0 = 2 * j;            // col within lane's 32-col block

                // x for col c0 (8 batch rows) and col c0+1, swizzled LDS.128 x4
                const float4 xa0 = *(const float4*)(xlane + ((( c0      << 5)      ) ^ xor_l));
                const float4 xb0 = *(const float4*)(xlane + ((( c0      << 5) | 16 ) ^ xor_l));
                const float4 xa1 = *(const float4*)(xlane + ((((c0 + 1) << 5)      ) ^ xor_l));
                const float4 xb1 = *(const float4*)(xlane + ((((c0 + 1) << 5) | 16 ) ^ xor_l));

                #pragma unroll
                for (int i = 0; i < ROWS_PER_WARP; i++) {
                    const int v = (&w[i].x)[jb];
                    // magic-mantissa: float(0x4B000000|n) = 2^23+n exactly;
                    // (2^23+n)-(2^23+8) = n-8 exactly (Sterbenz); one rounding in mul.
                    const int lob = (v & 15) | 0x4B000000;
                    const int hib = ((v >> 4) & 15) | 0x4B000000;
                    float2 q = fadd2(make_float2(__int_as_float(lob), __int_as_float(hib)), m8);
                    float2 wv = fmul2(q, make_float2(s[i], s[i]));  // (w_c0, w_c1)

                    acc[i][0] = ffma2(make_float2(wv.x, wv.x), make_float2(xa0.x, xa0.y), acc[i][0]);
                    acc[i][1] = ffma2(make_float2(wv.x, wv.x), make_float2(xa0.z, xa0.w), acc[i][1]);
                    acc[i][2] = ffma2(make_float2(wv.x, wv.x), make_float2(xb0.x, xb0.y), acc[i][2]);
                    acc[i][3] = ffma2(make_float2(wv.x, wv.x), make_float2(xb0.z, xb0.w), acc[i][3]);
                    acc[i][0] = ffma2(make_float2(wv.y, wv.y), make_float2(xa1.x, xa1.y), acc[i][0]);
                    acc[i][1] = ffma2(make_float2(wv.y, wv.y), make_float2(xa1.z, xa1.w), acc[i][1]);
                    acc[i][2] = ffma2(make_float2(wv.y, wv.y), make_float2(xb1.x, xb1.y), acc[i][2]);
                    acc[i][3] = ffma2(make_float2(wv.y, wv.y), make_float2(xb1.z, xb1.w), acc[i][3]);
                }
            }
        }
    }

    // Cross-lane reduction: butterfly over the 32 lanes (K blocks).
    #pragma unroll
    for (int i = 0; i < ROWS_PER_WARP; i++) {
        #pragma unroll
        for (int p = 0; p < 4; p++) {
            float2 v = acc[i][p];
            #pragma unroll
            for (int m = 16; m > 0; m >>= 1) {
                float2 o;
                o.x = __shfl_xor_sync(0xFFFFFFFF, v.x, m);
                o.y = __shfl_xor_sync(0xFFFFFFFF, v.y, m);
                v = fadd2(v, o);
            }
            acc[i][p] = v;
        }
    }
    if (lane == 0) {
        #pragma unroll
        for (int i = 0; i < ROWS_PER_WARP; i++) {
            const int row = rowbase + i;
            #pragma unroll
            for (int p = 0; p < 4; p++) {
                atomicAdd(&out[(size_t)(2 * p)     * OUTF + row], acc[i][p].x);
                atomicAdd(&out[(size_t)(2 * p + 1) * OUTF + row], acc[i][p].y);
            }
        }
    }
}

extern "C" void kernel_launch(void* const* d_in, const int* in_sizes, int n_in,
                              void* d_out, int out_size) {
    const float* x      = (const float*)d_in[0];
    const int*   packed = (const int*)d_in[1];
    const float* scales = (const float*)d_in[2];
    float*       out    = (float*)d_out;

    zero_kernel<<<(out_size + 255) / 256, 256>>>(out, out_size);

    dim3 grid(OUTF / ROWS_PER_CTA, SPLITK);   // (344, 2)
    qlin_kernel<<<grid, CTA_THREADS>>>(x, packed, scales, out);
}